// round 2
// baseline (speedup 1.0000x reference)
#include <cuda_runtime.h>
#include <math.h>

#define NMAX 150016
#define EMAX 3200064

// ---------------- static device scratch ----------------
__device__ float  g_dinv[NMAX];
__device__ int    g_cnt[NMAX];
__device__ int    g_cnt2[NMAX];
__device__ int    g_rs[NMAX + 2];
__device__ int    g_bsum[1024];
__device__ int2   g_csr[EMAX];          // {src, raw edge weight as bits}
__device__ float4 g_hw[NMAX * 16];      // projection output
__device__ float4 g_h [NMAX * 16];      // features ping
__device__ float4 g_h2[NMAX * 16];      // features pong

__device__ __forceinline__ void fma4(float4& a, float s, const float4& w) {
    a.x += s * w.x; a.y += s * w.y; a.z += s * w.z; a.w += s * w.w;
}

// ---------------- concat x=[U;I]  +  zero counters ----------------
__global__ void k_concat(const float4* __restrict__ U, const float4* __restrict__ I,
                         int nu16, int tot16, int N) {
    int i = blockIdx.x * blockDim.x + threadIdx.x;
    if (i < tot16) g_h[i] = (i < nu16) ? U[i] : I[i - nu16];
    if (i < N) { g_cnt[i] = 0; g_cnt2[i] = 0; }
}

// ---------------- per-dst edge counts (count only) ----------------
__global__ void k_cnt(const int* __restrict__ dst, int E) {
    for (int e = blockIdx.x * blockDim.x + threadIdx.x; e < E; e += gridDim.x * blockDim.x)
        atomicAdd(&g_cnt[dst[e]], 1);
}

// ---------------- exclusive scan of g_cnt -> g_rs ----------------
__global__ void k_scan1(int N) {
    __shared__ int sm[1024];
    int t = threadIdx.x;
    int i = blockIdx.x * 1024 + t;
    int x = (i < N) ? g_cnt[i] : 0;
    sm[t] = x;
    __syncthreads();
    for (int o = 1; o < 1024; o <<= 1) {
        int v = (t >= o) ? sm[t - o] : 0;
        __syncthreads();
        sm[t] += v;
        __syncthreads();
    }
    if (i < N) g_rs[i] = sm[t] - x;
    if (t == 1023) g_bsum[blockIdx.x] = sm[1023];
}

__global__ void k_scan2(int nb) {
    __shared__ int sm[1024];
    int t = threadIdx.x;
    int x = (t < nb) ? g_bsum[t] : 0;
    sm[t] = x;
    __syncthreads();
    for (int o = 1; o < 1024; o <<= 1) {
        int v = (t >= o) ? sm[t - o] : 0;
        __syncthreads();
        sm[t] += v;
        __syncthreads();
    }
    if (t < nb) g_bsum[t] = sm[t] - x;
}

__global__ void k_scan3(int N, int E) {
    int i = blockIdx.x * 1024 + threadIdx.x;
    if (i < N) g_rs[i] += g_bsum[blockIdx.x];
    if (i == 0) g_rs[N] = E;
}

// ---------------- CSR fill: bucket edges by dst (raw ew) ----------------
__global__ void k_fill(const int* __restrict__ src, const int* __restrict__ dst,
                       const float* __restrict__ ew, int E) {
    for (int e = blockIdx.x * blockDim.x + threadIdx.x; e < E; e += gridDim.x * blockDim.x) {
        int d = dst[e];
        int p = g_rs[d] + atomicAdd(&g_cnt2[d], 1);
        g_csr[p] = make_int2(src[e], __float_as_int(ew[e]));
    }
}

// ---------------- weighted degree from buckets -> dinv (no atomics) --------
__global__ __launch_bounds__(256) void k_degnorm(int N) {
    int t = threadIdx.x;
    int g = t & 15;
    int node = blockIdx.x * 16 + (t >> 4);
    unsigned mask = 0xFFFFu << (t & 16);
    if (node >= N) return;
    int e0 = g_rs[node], e1 = g_rs[node + 1];
    float s = 0.f;
    for (int i = e0 + g; i < e1; i += 16)
        s += __int_as_float(g_csr[i].y);
    s += __shfl_xor_sync(mask, s, 8, 16);
    s += __shfl_xor_sync(mask, s, 4, 16);
    s += __shfl_xor_sync(mask, s, 2, 16);
    s += __shfl_xor_sync(mask, s, 1, 16);
    if (g == 0) g_dinv[node] = rsqrtf(1.0f + s);   // +1 = self loop
}

// ---- fused conv layer: a = S h (gather) ; y = a@W + b ; LN ; ReLU ; + h ----
__global__ __launch_bounds__(256) void k_conv(const float4* __restrict__ h,
                                              const float* __restrict__ W,
                                              const float* __restrict__ bconv,
                                              const float* __restrict__ gam,
                                              const float* __restrict__ bet,
                                              float4* __restrict__ out, int N) {
    __shared__ __align__(16) float Xs[64][68];
    __shared__ __align__(16) float Ws[64][68];
    __shared__ __align__(16) float Hs[64][68];
    int t = threadIdx.x;
    int row0 = blockIdx.x * 64;

    // stage W
    const float4* W4 = (const float4*)W;
    for (int i = t; i < 1024; i += 256)
        *(float4*)&Ws[i >> 4][(i & 15) << 2] = W4[i];

    // gather phase: 16-lane group per node, 4 passes of 16 nodes
    int g = t & 15;
    unsigned mask16 = 0xFFFFu << (t & 16);
    for (int pass = 0; pass < 4; pass++) {
        int nl = pass * 16 + (t >> 4);
        int node = row0 + nl;
        float4 acc = make_float4(0.f, 0.f, 0.f, 0.f);
        float4 hs  = acc;
        float dvd = 0.f;
        if (node < N) {
            dvd = g_dinv[node];
            hs  = h[node * 16 + g];
            int e0 = g_rs[node], e1 = g_rs[node + 1];
            for (int base = e0; base < e1; base += 16) {
                int i = base + g;
                int s = 0; float wn = 0.f;
                if (i < e1) {
                    int2 ce = g_csr[i];
                    s = ce.x;
                    wn = g_dinv[s] * __int_as_float(ce.y);
                }
                int cnt = min(16, e1 - base);
                for (int j = 0; j < cnt; j++) {
                    int   ss = __shfl_sync(mask16, s,  j, 16);
                    float ww = __shfl_sync(mask16, wn, j, 16);
                    float4 v = h[ss * 16 + g];
                    fma4(acc, ww, v);
                }
            }
        }
        float4 a;
        a.x = dvd * (acc.x + dvd * hs.x);
        a.y = dvd * (acc.y + dvd * hs.y);
        a.z = dvd * (acc.z + dvd * hs.z);
        a.w = dvd * (acc.w + dvd * hs.w);
        *(float4*)&Xs[nl][g << 2] = a;
        *(float4*)&Hs[nl][g << 2] = hs;
    }
    __syncthreads();

    // GEMM: each thread = 1 row x 16 cols
    int r  = t >> 2;
    int cb = (t & 3) << 4;
    float4 a0 = make_float4(0.f,0.f,0.f,0.f), a1 = a0, a2 = a0, a3 = a0;
#pragma unroll
    for (int k = 0; k < 64; k++) {
        float xv = Xs[r][k];
        float4 w0 = *(const float4*)&Ws[k][cb +  0];
        float4 w1 = *(const float4*)&Ws[k][cb +  4];
        float4 w2 = *(const float4*)&Ws[k][cb +  8];
        float4 w3 = *(const float4*)&Ws[k][cb + 12];
        fma4(a0, xv, w0); fma4(a1, xv, w1); fma4(a2, xv, w2); fma4(a3, xv, w3);
    }

    // + conv bias
    const float4* b4 = (const float4*)bconv;
    int c4 = cb >> 2;
    float4 q;
    q = b4[c4+0]; a0.x+=q.x; a0.y+=q.y; a0.z+=q.z; a0.w+=q.w;
    q = b4[c4+1]; a1.x+=q.x; a1.y+=q.y; a1.z+=q.z; a1.w+=q.w;
    q = b4[c4+2]; a2.x+=q.x; a2.y+=q.y; a2.z+=q.z; a2.w+=q.w;
    q = b4[c4+3]; a3.x+=q.x; a3.y+=q.y; a3.z+=q.z; a3.w+=q.w;

    // LayerNorm over 64 (4 lanes x 16 each)
    int lane = t & 31;
    unsigned mask4 = 0xFu << (lane & ~3);
    float s = (a0.x+a0.y+a0.z+a0.w) + (a1.x+a1.y+a1.z+a1.w)
            + (a2.x+a2.y+a2.z+a2.w) + (a3.x+a3.y+a3.z+a3.w);
    s += __shfl_xor_sync(mask4, s, 1, 4);
    s += __shfl_xor_sync(mask4, s, 2, 4);
    float m = s * (1.0f / 64.0f);
    a0.x-=m; a0.y-=m; a0.z-=m; a0.w-=m;
    a1.x-=m; a1.y-=m; a1.z-=m; a1.w-=m;
    a2.x-=m; a2.y-=m; a2.z-=m; a2.w-=m;
    a3.x-=m; a3.y-=m; a3.z-=m; a3.w-=m;
    float vs = (a0.x*a0.x+a0.y*a0.y+a0.z*a0.z+a0.w*a0.w)
             + (a1.x*a1.x+a1.y*a1.y+a1.z*a1.z+a1.w*a1.w)
             + (a2.x*a2.x+a2.y*a2.y+a2.z*a2.z+a2.w*a2.w)
             + (a3.x*a3.x+a3.y*a3.y+a3.z*a3.z+a3.w*a3.w);
    vs += __shfl_xor_sync(mask4, vs, 1, 4);
    vs += __shfl_xor_sync(mask4, vs, 2, 4);
    float rstd = rsqrtf(vs * (1.0f / 64.0f) + 1e-5f);

    const float4* g4  = (const float4*)gam;
    const float4* be4 = (const float4*)bet;
    int grow = row0 + r;
    if (grow < N) {
        int o = grow * 16 + c4;
        float4 gg, be, hi, ov;
        gg = g4[c4+0]; be = be4[c4+0]; hi = *(const float4*)&Hs[r][cb + 0];
        ov.x = fmaxf(a0.x*rstd*gg.x + be.x, 0.f) + hi.x;
        ov.y = fmaxf(a0.y*rstd*gg.y + be.y, 0.f) + hi.y;
        ov.z = fmaxf(a0.z*rstd*gg.z + be.z, 0.f) + hi.z;
        ov.w = fmaxf(a0.w*rstd*gg.w + be.w, 0.f) + hi.w;
        out[o+0] = ov;
        gg = g4[c4+1]; be = be4[c4+1]; hi = *(const float4*)&Hs[r][cb + 4];
        ov.x = fmaxf(a1.x*rstd*gg.x + be.x, 0.f) + hi.x;
        ov.y = fmaxf(a1.y*rstd*gg.y + be.y, 0.f) + hi.y;
        ov.z = fmaxf(a1.z*rstd*gg.z + be.z, 0.f) + hi.z;
        ov.w = fmaxf(a1.w*rstd*gg.w + be.w, 0.f) + hi.w;
        out[o+1] = ov;
        gg = g4[c4+2]; be = be4[c4+2]; hi = *(const float4*)&Hs[r][cb + 8];
        ov.x = fmaxf(a2.x*rstd*gg.x + be.x, 0.f) + hi.x;
        ov.y = fmaxf(a2.y*rstd*gg.y + be.y, 0.f) + hi.y;
        ov.z = fmaxf(a2.z*rstd*gg.z + be.z, 0.f) + hi.z;
        ov.w = fmaxf(a2.w*rstd*gg.w + be.w, 0.f) + hi.w;
        out[o+2] = ov;
        gg = g4[c4+3]; be = be4[c4+3]; hi = *(const float4*)&Hs[r][cb + 12];
        ov.x = fmaxf(a3.x*rstd*gg.x + be.x, 0.f) + hi.x;
        ov.y = fmaxf(a3.y*rstd*gg.y + be.y, 0.f) + hi.y;
        ov.z = fmaxf(a3.z*rstd*gg.z + be.z, 0.f) + hi.z;
        ov.w = fmaxf(a3.w*rstd*gg.w + be.w, 0.f) + hi.w;
        out[o+3] = ov;
    }
}

// ---------------- plain GEMM (+bias) for projection ----------------
__global__ __launch_bounds__(256) void k_gemm(const float4* __restrict__ X,
                                              const float* __restrict__ W,
                                              const float* __restrict__ bias,
                                              float4* __restrict__ Y, int nrows) {
    __shared__ __align__(16) float Xs[64][68];
    __shared__ __align__(16) float Ws[64][68];
    int t = threadIdx.x;
    int row0 = blockIdx.x * 64;

    const float4* W4 = (const float4*)W;
    for (int i = t; i < 1024; i += 256)
        *(float4*)&Ws[i >> 4][(i & 15) << 2] = W4[i];
    for (int i = t; i < 1024; i += 256) {
        int r = i >> 4, c4 = i & 15;
        float4 v = make_float4(0.f, 0.f, 0.f, 0.f);
        if (row0 + r < nrows) v = X[(row0 + r) * 16 + c4];
        *(float4*)&Xs[r][c4 << 2] = v;
    }
    __syncthreads();

    int r  = t >> 2;
    int cb = (t & 3) << 4;
    float4 a0 = make_float4(0.f,0.f,0.f,0.f), a1 = a0, a2 = a0, a3 = a0;
#pragma unroll
    for (int k = 0; k < 64; k++) {
        float xv = Xs[r][k];
        float4 w0 = *(const float4*)&Ws[k][cb +  0];
        float4 w1 = *(const float4*)&Ws[k][cb +  4];
        float4 w2 = *(const float4*)&Ws[k][cb +  8];
        float4 w3 = *(const float4*)&Ws[k][cb + 12];
        fma4(a0, xv, w0); fma4(a1, xv, w1); fma4(a2, xv, w2); fma4(a3, xv, w3);
    }
    int grow = row0 + r;
    if (grow < nrows) {
        const float4* b4 = (const float4*)bias;
        int c4 = cb >> 2;
        float4 q;
        q = b4[c4+0]; a0.x+=q.x; a0.y+=q.y; a0.z+=q.z; a0.w+=q.w;
        q = b4[c4+1]; a1.x+=q.x; a1.y+=q.y; a1.z+=q.z; a1.w+=q.w;
        q = b4[c4+2]; a2.x+=q.x; a2.y+=q.y; a2.z+=q.z; a2.w+=q.w;
        q = b4[c4+3]; a3.x+=q.x; a3.y+=q.y; a3.z+=q.z; a3.w+=q.w;
        int o = grow * 16 + c4;
        Y[o + 0] = a0; Y[o + 1] = a1; Y[o + 2] = a2; Y[o + 3] = a3;
    }
}

// ---------------- scoring ----------------
__global__ __launch_bounds__(256) void k_score(const float4* __restrict__ hp,
                                               const int* __restrict__ users,
                                               const int* __restrict__ items,
                                               const float* __restrict__ bu,
                                               const float* __restrict__ bi,
                                               const float* __restrict__ mu,
                                               float* __restrict__ out, int B, int NU) {
    int t = threadIdx.x;
    int g = t & 15;
    int p = blockIdx.x * 16 + (t >> 4);
    unsigned mask = 0xFFFFu << (t & 16);
    if (p >= B) return;
    int u = users[p], it = items[p];
    float4 a = hp[u * 16 + g];
    float4 c = hp[(NU + it) * 16 + g];
    float s = a.x*c.x + a.y*c.y + a.z*c.z + a.w*c.w;
    s += __shfl_xor_sync(mask, s, 8, 16);
    s += __shfl_xor_sync(mask, s, 4, 16);
    s += __shfl_xor_sync(mask, s, 2, 16);
    s += __shfl_xor_sync(mask, s, 1, 16);
    if (g == 0) {
        float r = s + bu[u] + bi[it] + mu[0];
        out[p] = fminf(fmaxf(r, 1.0f), 5.0f);
    }
}

// ---------------- launch ----------------
extern "C" void kernel_launch(void* const* d_in, const int* in_sizes, int n_in,
                              void* d_out, int out_size) {
    const int*    users = (const int*)d_in[0];
    const int*    items = (const int*)d_in[1];
    const int*    eidx  = (const int*)d_in[2];
    const float*  ew    = (const float*)d_in[3];
    const float4* U     = (const float4*)d_in[4];
    const float4* I     = (const float4*)d_in[5];
    const float*  W0    = (const float*)d_in[6];
    const float*  b0    = (const float*)d_in[7];
    const float*  g0    = (const float*)d_in[8];
    const float*  be0   = (const float*)d_in[9];
    const float*  W1    = (const float*)d_in[10];
    const float*  b1    = (const float*)d_in[11];
    const float*  g1    = (const float*)d_in[12];
    const float*  be1   = (const float*)d_in[13];
    const float*  Wp    = (const float*)d_in[14];
    const float*  bp    = (const float*)d_in[15];
    const float*  bu    = (const float*)d_in[16];
    const float*  bi    = (const float*)d_in[17];
    const float*  mu    = (const float*)d_in[18];
    float* out = (float*)d_out;

    int B  = in_sizes[0];
    int E  = in_sizes[3];
    int NU = in_sizes[16];
    int NI = in_sizes[17];
    int N  = NU + NI;
    const int* esrc = eidx;
    const int* edst = eidx + E;

    float4 *p_hw, *p_h, *p_h2;
    cudaGetSymbolAddress((void**)&p_hw, g_hw);
    cudaGetSymbolAddress((void**)&p_h,  g_h);
    cudaGetSymbolAddress((void**)&p_h2, g_h2);

    int nb = (N + 1023) / 1024;

    k_concat<<<(N * 16 + 255) / 256, 256>>>(U, I, NU * 16, N * 16, N);
    k_cnt   <<<2048, 256>>>(edst, E);
    k_scan1 <<<nb, 1024>>>(N);
    k_scan2 <<<1, 1024>>>(nb);
    k_scan3 <<<nb, 1024>>>(N, E);
    k_fill  <<<2048, 256>>>(esrc, edst, ew, E);
    k_degnorm<<<(N + 15) / 16, 256>>>(N);

    // layer 0 (fused gather + gemm + LN + relu + residual)
    k_conv <<<(N + 63) / 64, 256>>>(p_h,  W0, b0, g0, be0, p_h2, N);
    // layer 1
    k_conv <<<(N + 63) / 64, 256>>>(p_h2, W1, b1, g1, be1, p_h,  N);
    // projection
    k_gemm <<<(N + 63) / 64, 256>>>(p_h, Wp, bp, p_hw, N);
    // scoring
    k_score<<<(B + 15) / 16, 256>>>(p_hw, users, items, bu, bi, mu, out, B, NU);
}

// round 3
// speedup vs baseline: 1.0072x; 1.0072x over previous
#include <cuda_runtime.h>
#include <cuda_fp16.h>
#include <math.h>

#define NMAX 150016
#define EMAX 3200064

// ---------------- static device scratch ----------------
__device__ float  g_deg[NMAX];
__device__ float  g_dinv[NMAX];
__device__ int    g_cnt[NMAX];
__device__ int    g_cnt2[NMAX];
__device__ int    g_rs[NMAX + 2];
__device__ int    g_bsum[1024];
__device__ int    g_bsumP[1024];
__device__ int    g_done;
__device__ int2   g_csr[EMAX];          // {src, raw edge weight bits}
__device__ float4 g_hw[NMAX * 16];      // projection output
__device__ float4 g_h [NMAX * 16];      // fp32 features ping
__device__ float4 g_h2[NMAX * 16];      // fp32 features pong
__device__ uint2  g_hh[NMAX * 16];      // fp16 gather copy (4 halves per entry)

__device__ __forceinline__ void fma4(float4& a, float s, const float4& w) {
    a.x += s * w.x; a.y += s * w.y; a.z += s * w.z; a.w += s * w.w;
}
__device__ __forceinline__ uint2 pack4h(const float4& v) {
    __half2 lo = __float22half2_rn(make_float2(v.x, v.y));
    __half2 hi = __float22half2_rn(make_float2(v.z, v.w));
    uint2 r;
    r.x = *(const unsigned*)&lo;
    r.y = *(const unsigned*)&hi;
    return r;
}

// ---------------- concat x=[U;I] (fp32 + fp16 copies) + zero counters ----------------
__global__ void k_concat(const float4* __restrict__ U, const float4* __restrict__ I,
                         int nu16, int tot16, int N) {
    int i = blockIdx.x * blockDim.x + threadIdx.x;
    if (i < tot16) {
        float4 v = (i < nu16) ? U[i] : I[i - nu16];
        g_h[i]  = v;
        g_hh[i] = pack4h(v);
    }
    if (i < N) { g_cnt[i] = 0; g_cnt2[i] = 0; g_deg[i] = 1.0f; }  // 1 = self loop
    if (i == 0) g_done = 0;
}

// ---------------- per-dst counts + weighted degree ----------------
__global__ void k_cnt(const int* __restrict__ dst, const float* __restrict__ ew, int E) {
    for (int e = blockIdx.x * blockDim.x + threadIdx.x; e < E; e += gridDim.x * blockDim.x) {
        int d = dst[e];
        atomicAdd(&g_cnt[d], 1);
        atomicAdd(&g_deg[d], ew[e]);
    }
}

// ---------------- scan (fused): local exclusive + dinv + last-block bsum scan ----------
__global__ void k_scan(int N, int nb) {
    __shared__ int sm[1024];
    __shared__ bool isLast;
    int t = threadIdx.x;
    int i = blockIdx.x * 1024 + t;
    int x = (i < N) ? g_cnt[i] : 0;
    sm[t] = x;
    __syncthreads();
    for (int o = 1; o < 1024; o <<= 1) {
        int v = (t >= o) ? sm[t - o] : 0;
        __syncthreads();
        sm[t] += v;
        __syncthreads();
    }
    if (i < N) {
        g_rs[i] = sm[t] - x;                    // block-local exclusive
        g_dinv[i] = rsqrtf(g_deg[i]);           // deg includes self loop (init 1)
    }
    if (t == 1023) g_bsum[blockIdx.x] = sm[1023];

    __threadfence();
    if (t == 0) isLast = (atomicAdd(&g_done, 1) == gridDim.x - 1);
    __syncthreads();
    if (isLast) {
        int y = (t < nb) ? g_bsum[t] : 0;
        sm[t] = y;
        __syncthreads();
        for (int o = 1; o < 1024; o <<= 1) {
            int v = (t >= o) ? sm[t - o] : 0;
            __syncthreads();
            sm[t] += v;
            __syncthreads();
        }
        if (t < nb) g_bsumP[t] = sm[t] - y;     // exclusive block offsets
    }
}

// ---------------- CSR fill (global slot = local rs + block offset + atomic) ------------
__global__ void k_fill(const int* __restrict__ src, const int* __restrict__ dst,
                       const float* __restrict__ ew, int E) {
    for (int e = blockIdx.x * blockDim.x + threadIdx.x; e < E; e += gridDim.x * blockDim.x) {
        int d = dst[e];
        int p = g_rs[d] + g_bsumP[d >> 10] + atomicAdd(&g_cnt2[d], 1);
        g_csr[p] = make_int2(src[e], __float_as_int(ew[e]));
    }
}

// ---- fused conv: a = S h (fp16 gather, fp32 acc); y = a@W + b; LN; ReLU; +h ----
__global__ __launch_bounds__(256) void k_conv(const float4* __restrict__ h,
                                              const uint2*  __restrict__ hh,
                                              const float* __restrict__ W,
                                              const float* __restrict__ bconv,
                                              const float* __restrict__ gam,
                                              const float* __restrict__ bet,
                                              float4* __restrict__ out,
                                              uint2*  __restrict__ outh,
                                              int N, int E) {
    __shared__ __align__(16) float Xs[64][68];
    __shared__ __align__(16) float Ws[64][68];
    __shared__ __align__(16) float Hs[64][68];
    int t = threadIdx.x;
    int row0 = blockIdx.x * 64;

    const float4* W4 = (const float4*)W;
    for (int i = t; i < 1024; i += 256)
        *(float4*)&Ws[i >> 4][(i & 15) << 2] = W4[i];

    int g = t & 15;
    unsigned mask16 = 0xFFFFu << (t & 16);
    for (int pass = 0; pass < 4; pass++) {
        int nl = pass * 16 + (t >> 4);
        int node = row0 + nl;
        float4 acc = make_float4(0.f, 0.f, 0.f, 0.f);
        float4 hs  = acc;
        float dvd = 0.f;
        if (node < N) {
            dvd = g_dinv[node];
            hs  = h[node * 16 + g];
            int e0 = g_rs[node] + g_bsumP[node >> 10];
            int e1 = (node + 1 < N) ? (g_rs[node + 1] + g_bsumP[(node + 1) >> 10]) : E;
            for (int base = e0; base < e1; base += 16) {
                int i = base + g;
                int s = 0; float wn = 0.f;
                if (i < e1) {
                    int2 ce = g_csr[i];
                    s = ce.x;
                    wn = g_dinv[s] * __int_as_float(ce.y);
                }
                int cnt = min(16, e1 - base);
                for (int j = 0; j < cnt; j++) {
                    int   ss = __shfl_sync(mask16, s,  j, 16);
                    float ww = __shfl_sync(mask16, wn, j, 16);
                    uint2 pv = hh[ss * 16 + g];
                    float2 f0 = __half22float2(*(const __half2*)&pv.x);
                    float2 f1 = __half22float2(*(const __half2*)&pv.y);
                    acc.x += ww * f0.x; acc.y += ww * f0.y;
                    acc.z += ww * f1.x; acc.w += ww * f1.y;
                }
            }
        }
        float4 a;
        a.x = dvd * (acc.x + dvd * hs.x);
        a.y = dvd * (acc.y + dvd * hs.y);
        a.z = dvd * (acc.z + dvd * hs.z);
        a.w = dvd * (acc.w + dvd * hs.w);
        *(float4*)&Xs[nl][g << 2] = a;
        *(float4*)&Hs[nl][g << 2] = hs;
    }
    __syncthreads();

    // GEMM: thread = 1 row x 16 cols
    int r  = t >> 2;
    int cb = (t & 3) << 4;
    float4 a0 = make_float4(0.f,0.f,0.f,0.f), a1 = a0, a2 = a0, a3 = a0;
#pragma unroll
    for (int k = 0; k < 64; k++) {
        float xv = Xs[r][k];
        fma4(a0, xv, *(const float4*)&Ws[k][cb +  0]);
        fma4(a1, xv, *(const float4*)&Ws[k][cb +  4]);
        fma4(a2, xv, *(const float4*)&Ws[k][cb +  8]);
        fma4(a3, xv, *(const float4*)&Ws[k][cb + 12]);
    }

    const float4* b4 = (const float4*)bconv;
    int c4 = cb >> 2;
    float4 q;
    q = b4[c4+0]; a0.x+=q.x; a0.y+=q.y; a0.z+=q.z; a0.w+=q.w;
    q = b4[c4+1]; a1.x+=q.x; a1.y+=q.y; a1.z+=q.z; a1.w+=q.w;
    q = b4[c4+2]; a2.x+=q.x; a2.y+=q.y; a2.z+=q.z; a2.w+=q.w;
    q = b4[c4+3]; a3.x+=q.x; a3.y+=q.y; a3.z+=q.z; a3.w+=q.w;

    // LayerNorm over 64 (4 lanes x 16)
    int lane = t & 31;
    unsigned mask4 = 0xFu << (lane & ~3);
    float s = (a0.x+a0.y+a0.z+a0.w) + (a1.x+a1.y+a1.z+a1.w)
            + (a2.x+a2.y+a2.z+a2.w) + (a3.x+a3.y+a3.z+a3.w);
    s += __shfl_xor_sync(mask4, s, 1, 4);
    s += __shfl_xor_sync(mask4, s, 2, 4);
    float m = s * (1.0f / 64.0f);
    a0.x-=m; a0.y-=m; a0.z-=m; a0.w-=m;
    a1.x-=m; a1.y-=m; a1.z-=m; a1.w-=m;
    a2.x-=m; a2.y-=m; a2.z-=m; a2.w-=m;
    a3.x-=m; a3.y-=m; a3.z-=m; a3.w-=m;
    float vs = (a0.x*a0.x+a0.y*a0.y+a0.z*a0.z+a0.w*a0.w)
             + (a1.x*a1.x+a1.y*a1.y+a1.z*a1.z+a1.w*a1.w)
             + (a2.x*a2.x+a2.y*a2.y+a2.z*a2.z+a2.w*a2.w)
             + (a3.x*a3.x+a3.y*a3.y+a3.z*a3.z+a3.w*a3.w);
    vs += __shfl_xor_sync(mask4, vs, 1, 4);
    vs += __shfl_xor_sync(mask4, vs, 2, 4);
    float rstd = rsqrtf(vs * (1.0f / 64.0f) + 1e-5f);

    const float4* g4  = (const float4*)gam;
    const float4* be4 = (const float4*)bet;
    int grow = row0 + r;
    if (grow < N) {
        int o = grow * 16 + c4;
        float4 gg, be, hi, ov;
        gg = g4[c4+0]; be = be4[c4+0]; hi = *(const float4*)&Hs[r][cb + 0];
        ov.x = fmaxf(a0.x*rstd*gg.x + be.x, 0.f) + hi.x;
        ov.y = fmaxf(a0.y*rstd*gg.y + be.y, 0.f) + hi.y;
        ov.z = fmaxf(a0.z*rstd*gg.z + be.z, 0.f) + hi.z;
        ov.w = fmaxf(a0.w*rstd*gg.w + be.w, 0.f) + hi.w;
        out[o+0] = ov; outh[o+0] = pack4h(ov);
        gg = g4[c4+1]; be = be4[c4+1]; hi = *(const float4*)&Hs[r][cb + 4];
        ov.x = fmaxf(a1.x*rstd*gg.x + be.x, 0.f) + hi.x;
        ov.y = fmaxf(a1.y*rstd*gg.y + be.y, 0.f) + hi.y;
        ov.z = fmaxf(a1.z*rstd*gg.z + be.z, 0.f) + hi.z;
        ov.w = fmaxf(a1.w*rstd*gg.w + be.w, 0.f) + hi.w;
        out[o+1] = ov; outh[o+1] = pack4h(ov);
        gg = g4[c4+2]; be = be4[c4+2]; hi = *(const float4*)&Hs[r][cb + 8];
        ov.x = fmaxf(a2.x*rstd*gg.x + be.x, 0.f) + hi.x;
        ov.y = fmaxf(a2.y*rstd*gg.y + be.y, 0.f) + hi.y;
        ov.z = fmaxf(a2.z*rstd*gg.z + be.z, 0.f) + hi.z;
        ov.w = fmaxf(a2.w*rstd*gg.w + be.w, 0.f) + hi.w;
        out[o+2] = ov; outh[o+2] = pack4h(ov);
        gg = g4[c4+3]; be = be4[c4+3]; hi = *(const float4*)&Hs[r][cb + 12];
        ov.x = fmaxf(a3.x*rstd*gg.x + be.x, 0.f) + hi.x;
        ov.y = fmaxf(a3.y*rstd*gg.y + be.y, 0.f) + hi.y;
        ov.z = fmaxf(a3.z*rstd*gg.z + be.z, 0.f) + hi.z;
        ov.w = fmaxf(a3.w*rstd*gg.w + be.w, 0.f) + hi.w;
        out[o+3] = ov; outh[o+3] = pack4h(ov);
    }
}

// ---------------- plain GEMM (+bias) for projection ----------------
__global__ __launch_bounds__(256) void k_gemm(const float4* __restrict__ X,
                                              const float* __restrict__ W,
                                              const float* __restrict__ bias,
                                              float4* __restrict__ Y, int nrows) {
    __shared__ __align__(16) float Xs[64][68];
    __shared__ __align__(16) float Ws[64][68];
    int t = threadIdx.x;
    int row0 = blockIdx.x * 64;

    const float4* W4 = (const float4*)W;
    for (int i = t; i < 1024; i += 256)
        *(float4*)&Ws[i >> 4][(i & 15) << 2] = W4[i];
    for (int i = t; i < 1024; i += 256) {
        int r = i >> 4, c4 = i & 15;
        float4 v = make_float4(0.f, 0.f, 0.f, 0.f);
        if (row0 + r < nrows) v = X[(row0 + r) * 16 + c4];
        *(float4*)&Xs[r][c4 << 2] = v;
    }
    __syncthreads();

    int r  = t >> 2;
    int cb = (t & 3) << 4;
    float4 a0 = make_float4(0.f,0.f,0.f,0.f), a1 = a0, a2 = a0, a3 = a0;
#pragma unroll
    for (int k = 0; k < 64; k++) {
        float xv = Xs[r][k];
        fma4(a0, xv, *(const float4*)&Ws[k][cb +  0]);
        fma4(a1, xv, *(const float4*)&Ws[k][cb +  4]);
        fma4(a2, xv, *(const float4*)&Ws[k][cb +  8]);
        fma4(a3, xv, *(const float4*)&Ws[k][cb + 12]);
    }
    int grow = row0 + r;
    if (grow < nrows) {
        const float4* b4 = (const float4*)bias;
        int c4 = cb >> 2;
        float4 q;
        q = b4[c4+0]; a0.x+=q.x; a0.y+=q.y; a0.z+=q.z; a0.w+=q.w;
        q = b4[c4+1]; a1.x+=q.x; a1.y+=q.y; a1.z+=q.z; a1.w+=q.w;
        q = b4[c4+2]; a2.x+=q.x; a2.y+=q.y; a2.z+=q.z; a2.w+=q.w;
        q = b4[c4+3]; a3.x+=q.x; a3.y+=q.y; a3.z+=q.z; a3.w+=q.w;
        int o = grow * 16 + c4;
        Y[o + 0] = a0; Y[o + 1] = a1; Y[o + 2] = a2; Y[o + 3] = a3;
    }
}

// ---------------- scoring ----------------
__global__ __launch_bounds__(256) void k_score(const float4* __restrict__ hp,
                                               const int* __restrict__ users,
                                               const int* __restrict__ items,
                                               const float* __restrict__ bu,
                                               const float* __restrict__ bi,
                                               const float* __restrict__ mu,
                                               float* __restrict__ out, int B, int NU) {
    int t = threadIdx.x;
    int g = t & 15;
    int p = blockIdx.x * 16 + (t >> 4);
    unsigned mask = 0xFFFFu << (t & 16);
    if (p >= B) return;
    int u = users[p], it = items[p];
    float4 a = hp[u * 16 + g];
    float4 c = hp[(NU + it) * 16 + g];
    float s = a.x*c.x + a.y*c.y + a.z*c.z + a.w*c.w;
    s += __shfl_xor_sync(mask, s, 8, 16);
    s += __shfl_xor_sync(mask, s, 4, 16);
    s += __shfl_xor_sync(mask, s, 2, 16);
    s += __shfl_xor_sync(mask, s, 1, 16);
    if (g == 0) {
        float r = s + bu[u] + bi[it] + mu[0];
        out[p] = fminf(fmaxf(r, 1.0f), 5.0f);
    }
}

// ---------------- launch ----------------
extern "C" void kernel_launch(void* const* d_in, const int* in_sizes, int n_in,
                              void* d_out, int out_size) {
    const int*    users = (const int*)d_in[0];
    const int*    items = (const int*)d_in[1];
    const int*    eidx  = (const int*)d_in[2];
    const float*  ew    = (const float*)d_in[3];
    const float4* U     = (const float4*)d_in[4];
    const float4* I     = (const float4*)d_in[5];
    const float*  W0    = (const float*)d_in[6];
    const float*  b0    = (const float*)d_in[7];
    const float*  g0    = (const float*)d_in[8];
    const float*  be0   = (const float*)d_in[9];
    const float*  W1    = (const float*)d_in[10];
    const float*  b1    = (const float*)d_in[11];
    const float*  g1    = (const float*)d_in[12];
    const float*  be1   = (const float*)d_in[13];
    const float*  Wp    = (const float*)d_in[14];
    const float*  bp    = (const float*)d_in[15];
    const float*  bu    = (const float*)d_in[16];
    const float*  bi    = (const float*)d_in[17];
    const float*  mu    = (const float*)d_in[18];
    float* out = (float*)d_out;

    int B  = in_sizes[0];
    int E  = in_sizes[3];
    int NU = in_sizes[16];
    int NI = in_sizes[17];
    int N  = NU + NI;
    const int* esrc = eidx;
    const int* edst = eidx + E;

    float4 *p_hw, *p_h, *p_h2;
    uint2  *p_hh, *p_hh2;
    cudaGetSymbolAddress((void**)&p_hw,  g_hw);
    cudaGetSymbolAddress((void**)&p_h,   g_h);
    cudaGetSymbolAddress((void**)&p_h2,  g_h2);
    cudaGetSymbolAddress((void**)&p_hh,  g_hh);
    p_hh2 = p_hh;   // fp16 buffer reused: conv reads it fully before epilogue overwrites?  NO — separate needed
    // NOTE: conv reads hh for gather while epilogue writes outh; same buffer would race.
    // Use g_hw's storage as the second fp16 buffer (it is only needed later, and sized 38MB >= 19MB).
    p_hh2 = (uint2*)p_hw;

    int nb = (N + 1023) / 1024;

    k_concat<<<(N * 16 + 255) / 256, 256>>>(U, I, NU * 16, N * 16, N);
    k_cnt   <<<2048, 256>>>(edst, ew, E);
    k_scan  <<<nb, 1024>>>(N, nb);
    k_fill  <<<2048, 256>>>(esrc, edst, ew, E);

    // layer 0: read fp16 g_hh, write fp32 g_h2 + fp16 into p_hh2 (aliased over g_hw)
    k_conv <<<(N + 63) / 64, 256>>>(p_h,  p_hh,  W0, b0, g0, be0, p_h2, p_hh2, N, E);
    // layer 1: read fp16 p_hh2, write fp32 g_h + fp16 back into g_hh (no longer read)
    k_conv <<<(N + 63) / 64, 256>>>(p_h2, p_hh2, W1, b1, g1, be1, p_h,  p_hh,  N, E);
    // projection (fp32) — overwrites g_hw AFTER conv layer 1 consumed p_hh2
    k_gemm <<<(N + 63) / 64, 256>>>(p_h, Wp, bp, p_hw, N);
    // scoring
    k_score<<<(B + 15) / 16, 256>>>(p_hw, users, items, bu, bi, mu, out, B, NU);
}